// round 15
// baseline (speedup 1.0000x reference)
#include <cuda_runtime.h>
#include <cuda_fp16.h>
#include <cstdint>
#include <cstddef>

#define MAXN 100000
#define MAXE 800000
#define D128 128

// ---------------- scratch (no allocs allowed) ----------------
__device__ __half d_bufA[(size_t)MAXN * D128];  // Pf (fp16)
__device__ __half d_bufB[(size_t)MAXN * D128];  // Pv
__device__ __half d_bufC[(size_t)MAXN * D128];  // Qf
__device__ __half d_bufD[(size_t)MAXN * D128];  // Qv
__device__ __half d_aggrF[(size_t)MAXN * D128]; // fp16 aggregates
__device__ __half d_aggrV[(size_t)MAXN * D128];
__device__ __half d_Vc[(size_t)MAXN * D128];    // fp16 layer-0 outputs
__device__ __half d_Fc[(size_t)MAXN * D128];
__device__ __half d_WTh[294912];                // pre-transposed weights (fp16)
__device__ float d_gatt[64 * D128];
__device__ float d_gatt2[64 * D128];
__device__ float d_gate[MAXN];
__device__ float d_ebuf[MAXN];
__device__ int   d_offF[MAXN + 1];
__device__ int   d_offV[MAXN + 1];
__device__ int   d_curF[MAXN];
__device__ int   d_curV[MAXN];
__device__ int   d_adjF[MAXE];
__device__ int   d_adjV[MAXE];
__device__ int   d_bnd[65 + 4];
__device__ int   d_partF[132];
__device__ int   d_partV[132];

// ---------------- PTX helpers ----------------
__device__ __forceinline__ uint32_t smem_u32(const void* p) {
    uint32_t a;
    asm("{ .reg .u64 t; cvta.to.shared.u64 t, %1; cvt.u32.u64 %0, t; }" : "=r"(a) : "l"(p));
    return a;
}
__device__ __forceinline__ void ldsm_x4(uint32_t& r0, uint32_t& r1, uint32_t& r2, uint32_t& r3, uint32_t addr) {
    asm volatile("ldmatrix.sync.aligned.m8n8.x4.shared.b16 {%0,%1,%2,%3}, [%4];"
                 : "=r"(r0), "=r"(r1), "=r"(r2), "=r"(r3) : "r"(addr));
}
__device__ __forceinline__ void mma_f16(float* c, const uint32_t* a, uint32_t b0, uint32_t b1) {
    asm volatile(
        "mma.sync.aligned.m16n8k16.row.col.f32.f16.f16.f32 "
        "{%0,%1,%2,%3}, {%4,%5,%6,%7}, {%8,%9}, {%0,%1,%2,%3};"
        : "+f"(c[0]), "+f"(c[1]), "+f"(c[2]), "+f"(c[3])
        : "r"(a[0]), "r"(a[1]), "r"(a[2]), "r"(a[3]), "r"(b0), "r"(b1));
}

// ---------------- multi-job fp16 GEMM: 256 thr, warp tile 32x64, BK=32, 2 CTA/SM ----------------
struct GJob {
    const void* A0; const void* A1; const __half* WT;
    const float* bias; const void* Res;
    void* Out0; void* Out1;
    int M; int relu; int out16; int a0h; int a1h; int resh;
};
struct GParams { GJob j[2]; int K; };

#define PITH 40
#define STGH (2 * 128 * PITH)
__global__ void __launch_bounds__(256, 2) gemm_mma(GParams P)
{
    extern __shared__ __align__(16) char smc[];
    const GJob J = P.j[blockIdx.z];
    const int K = P.K;
    const int M = J.M;
    const int rowBase = blockIdx.x * 128;
    if (rowBase >= M) return;
    const int tid  = threadIdx.x;
    const int lane = tid & 31;
    const int warp = tid >> 5;
    const int wm = warp & 3;
    const int wn = warp >> 2;
    const __half* WTb = J.WT + (size_t)blockIdx.y * 128 * K;
    void* Outv = (blockIdx.y == 0) ? J.Out0 : J.Out1;

    const int lr = tid >> 3;
    const int lc = (tid & 7) << 2;

    const uint32_t smbase = smem_u32(smc);
    const uint32_t aoffB = (uint32_t)(((wm * 32 + (lane & 15)) * PITH + ((lane >> 4) << 3)) * 2);
    const uint32_t boffB = (uint32_t)(((wn * 64 + ((lane >> 4) << 3) + (lane & 7)) * PITH
                                      + (((lane >> 3) & 1) << 3)) * 2);

    float acc[2][8][4];
#pragma unroll
    for (int mt = 0; mt < 2; mt++)
#pragma unroll
        for (int nt = 0; nt < 8; nt++)
#pragma unroll
            for (int j = 0; j < 4; j++) acc[mt][nt][j] = 0.f;

    const int nch = K >> 5;
    float4 ra[4];
    uint2 rh[4];
    int cur_ah = 0;

#define LDG_A(ck)                                                                      \
    {                                                                                  \
        int kg = (ck) * 32;                                                            \
        const void* Ap = J.A0; cur_ah = J.a0h;                                         \
        if (kg >= 128) { Ap = J.A1; cur_ah = J.a1h; kg -= 128; }                       \
        if (cur_ah) {                                                                  \
            const __half* A16 = (const __half*)Ap;                                     \
            _Pragma("unroll")                                                          \
            for (int h = 0; h < 4; h++) {                                              \
                int r = lr + 32 * h;                                                   \
                int grow = rowBase + r;                                                \
                uint2 z = make_uint2(0u, 0u);                                          \
                if (grow < M) z = *reinterpret_cast<const uint2*>(A16 + (size_t)grow * 128 + kg + lc); \
                rh[h] = z;                                                             \
            }                                                                          \
        } else {                                                                       \
            const float* A32 = (const float*)Ap;                                       \
            _Pragma("unroll")                                                          \
            for (int h = 0; h < 4; h++) {                                              \
                int r = lr + 32 * h;                                                   \
                int grow = rowBase + r;                                                \
                float4 v = make_float4(0.f, 0.f, 0.f, 0.f);                            \
                if (grow < M) v = *reinterpret_cast<const float4*>(A32 + (size_t)grow * 128 + kg + lc); \
                ra[h] = v;                                                             \
            }                                                                          \
        }                                                                              \
    }

#define STS_A(s)                                                                       \
    {                                                                                  \
        char* stA = smc + (size_t)(s) * STGH * 2;                                      \
        if (cur_ah) {                                                                  \
            _Pragma("unroll")                                                          \
            for (int h = 0; h < 4; h++) {                                              \
                int r = lr + 32 * h;                                                   \
                *reinterpret_cast<uint2*>(stA + (size_t)(r * PITH + lc) * 2) = rh[h];  \
            }                                                                          \
        } else {                                                                       \
            _Pragma("unroll")                                                          \
            for (int h = 0; h < 4; h++) {                                              \
                int r = lr + 32 * h;                                                   \
                __half2 h0 = __floats2half2_rn(ra[h].x, ra[h].y);                      \
                __half2 h1 = __floats2half2_rn(ra[h].z, ra[h].w);                      \
                uint2 u;                                                               \
                u.x = *reinterpret_cast<uint32_t*>(&h0);                               \
                u.y = *reinterpret_cast<uint32_t*>(&h1);                               \
                *reinterpret_cast<uint2*>(stA + (size_t)(r * PITH + lc) * 2) = u;      \
            }                                                                          \
        }                                                                              \
    }

#define CPA_B(ck, s)                                                                   \
    {                                                                                  \
        uint32_t stB = smbase + (uint32_t)((s) * STGH + 128 * PITH) * 2;               \
        int n = tid >> 1;                                                              \
        int q = tid & 1;                                                               \
        const __half* s0 = WTb + (size_t)n * K + (ck) * 32 + q * 16;                   \
        uint32_t d0 = stB + (uint32_t)(n * PITH + q * 16) * 2;                         \
        asm volatile("cp.async.ca.shared.global [%0], [%1], 16;" :: "r"(d0), "l"(s0)); \
        asm volatile("cp.async.ca.shared.global [%0], [%1], 16;" :: "r"(d0 + 16), "l"(s0 + 8)); \
        asm volatile("cp.async.commit_group;");                                        \
    }

    LDG_A(0);
    CPA_B(0, 0);
    STS_A(0);
    asm volatile("cp.async.wait_group 0;" ::: "memory");
    __syncthreads();

    for (int ck = 0; ck < nch; ck++) {
        const int s = ck & 1;
        if (ck + 1 < nch) {
            LDG_A(ck + 1);
            CPA_B(ck + 1, s ^ 1);
        }
        const uint32_t smA = smbase + (uint32_t)(s * STGH) * 2;
        const uint32_t smB = smA + (uint32_t)(128 * PITH) * 2;
#pragma unroll
        for (int kstep = 0; kstep < 2; kstep++) {
            uint32_t a[2][4];
            ldsm_x4(a[0][0], a[0][1], a[0][2], a[0][3], smA + aoffB + kstep * 32);
            ldsm_x4(a[1][0], a[1][1], a[1][2], a[1][3], smA + aoffB + 16 * PITH * 2 + kstep * 32);
            uint32_t b[4][4];
#pragma unroll
            for (int p = 0; p < 4; p++)
                ldsm_x4(b[p][0], b[p][1], b[p][2], b[p][3],
                        smB + boffB + (uint32_t)(p * 16 * PITH * 2) + kstep * 32);
#pragma unroll
            for (int mt = 0; mt < 2; mt++)
#pragma unroll
                for (int nt = 0; nt < 8; nt++)
                    mma_f16(acc[mt][nt], a[mt], b[nt >> 1][(nt & 1) * 2], b[nt >> 1][(nt & 1) * 2 + 1]);
        }
        if (ck + 1 < nch) {
            STS_A(s ^ 1);
            asm volatile("cp.async.wait_group 0;" ::: "memory");
            __syncthreads();
        }
    }

    // epilogue
    const int col2 = (lane & 3) * 2;
#pragma unroll
    for (int mt = 0; mt < 2; mt++) {
        const int r0 = rowBase + wm * 32 + mt * 16 + (lane >> 2);
#pragma unroll
        for (int nt = 0; nt < 8; nt++) {
            int col = wn * 64 + nt * 8 + col2;
            float v0 = acc[mt][nt][0], v1 = acc[mt][nt][1];
            float v2 = acc[mt][nt][2], v3 = acc[mt][nt][3];
            if (J.bias) {
                float b0 = J.bias[col], b1 = J.bias[col + 1];
                v0 += b0; v1 += b1; v2 += b0; v3 += b1;
            }
            if (J.relu) {
                v0 = fmaxf(v0, 0.f); v1 = fmaxf(v1, 0.f);
                v2 = fmaxf(v2, 0.f); v3 = fmaxf(v3, 0.f);
            }
            if (J.Res) {
                if (J.resh) {
                    const __half* R = (const __half*)J.Res;
                    if (r0 < M) {
                        __half2 hh = *reinterpret_cast<const __half2*>(R + (size_t)r0 * 128 + col);
                        float2 rr = __half22float2(hh);
                        v0 += rr.x; v1 += rr.y;
                    }
                    if (r0 + 8 < M) {
                        __half2 hh = *reinterpret_cast<const __half2*>(R + (size_t)(r0 + 8) * 128 + col);
                        float2 rr = __half22float2(hh);
                        v2 += rr.x; v3 += rr.y;
                    }
                } else {
                    const float* R = (const float*)J.Res;
                    if (r0 < M) {
                        float2 rr = *reinterpret_cast<const float2*>(R + (size_t)r0 * 128 + col);
                        v0 += rr.x; v1 += rr.y;
                    }
                    if (r0 + 8 < M) {
                        float2 rr = *reinterpret_cast<const float2*>(R + (size_t)(r0 + 8) * 128 + col);
                        v2 += rr.x; v3 += rr.y;
                    }
                }
            }
            if (J.out16) {
                __half* Out = (__half*)Outv;
                if (r0 < M)
                    *reinterpret_cast<__half2*>(Out + (size_t)r0 * 128 + col) = __floats2half2_rn(v0, v1);
                if (r0 + 8 < M)
                    *reinterpret_cast<__half2*>(Out + (size_t)(r0 + 8) * 128 + col) = __floats2half2_rn(v2, v3);
            } else {
                float* Out = (float*)Outv;
                if (r0 < M)
                    *reinterpret_cast<float2*>(Out + (size_t)r0 * 128 + col) = make_float2(v0, v1);
                if (r0 + 8 < M)
                    *reinterpret_cast<float2*>(Out + (size_t)(r0 + 8) * 128 + col) = make_float2(v2, v3);
            }
        }
    }
}

// ---------------- fused weight transposes ----------------
struct TJobs {
    const float* src[16];
    __half* dst[16];
    int K[16];
};
__global__ void transpose_all(TJobs jobs)
{
    __shared__ float t[32][33];
    const int j = blockIdx.z;
    const int K = jobs.K[j];
    const int kb = blockIdx.x * 32;
    if (kb >= K) return;
    const float* src = jobs.src[j];
    __half* dst = jobs.dst[j];
    const int nb = blockIdx.y * 32;
    const int x = threadIdx.x, y = threadIdx.y;
    for (int yy = y; yy < 32; yy += 8) t[yy][x] = src[(size_t)(kb + yy) * 128 + nb + x];
    __syncthreads();
    for (int yy = y; yy < 32; yy += 8)
        dst[(size_t)(nb + yy) * K + kb + x] = __float2half_rn(t[x][yy]);
}

// ---------------- CSR build ----------------
__global__ void hist_kernel(const int* __restrict__ src, const int* __restrict__ dst, int E,
                            int* __restrict__ degV, int* __restrict__ degF)
{
    int e = blockIdx.x * blockDim.x + threadIdx.x;
    if (e < E) {
        atomicAdd(&degV[src[e]], 1);
        atomicAdd(&degF[dst[e]], 1);
    }
}

__device__ __forceinline__ int4 load4_guard(const int* p, int base, int N)
{
    int4 v = make_int4(0, 0, 0, 0);
    if (base + 3 < N) v = *reinterpret_cast<const int4*>(p + base);
    else if (base < N) {
        v.x = p[base];
        if (base + 1 < N) v.y = p[base + 1];
        if (base + 2 < N) v.z = p[base + 2];
    }
    return v;
}

__global__ void scan_p1(const int* __restrict__ degF, int NF, int* __restrict__ pF,
                        const int* __restrict__ degV, int NV, int* __restrict__ pV)
{
    const int* deg = blockIdx.y ? degV : degF;
    int* part = blockIdx.y ? pV : pF;
    const int N = blockIdx.y ? NV : NF;
    if (blockIdx.x * 1024 >= N) return;
    int base = blockIdx.x * 1024 + threadIdx.x * 4;
    int4 v = load4_guard(deg, base, N);
    int s = v.x + v.y + v.z + v.w;
#pragma unroll
    for (int d = 16; d; d >>= 1) s += __shfl_down_sync(~0u, s, d);
    __shared__ int ws[8];
    if ((threadIdx.x & 31) == 0) ws[threadIdx.x >> 5] = s;
    __syncthreads();
    if (threadIdx.x == 0) {
        int tt = 0;
#pragma unroll
        for (int i = 0; i < 8; i++) tt += ws[i];
        part[blockIdx.x] = tt;
    }
}

__global__ void scan_p2(int* __restrict__ pF, int nbF, int* __restrict__ pV, int nbV)
{
    __shared__ int sh[128];
    const int t = threadIdx.x;
    for (int sel = 0; sel < 2; sel++) {
        int* p = sel ? pV : pF;
        const int nb = sel ? nbV : nbF;
        int v = (t < nb) ? p[t] : 0;
        sh[t] = v;
        __syncthreads();
        int x = v;
        for (int o = 1; o < 128; o <<= 1) {
            int y = (t >= o) ? sh[t - o] : 0;
            __syncthreads();
            x += y;
            sh[t] = x;
            __syncthreads();
        }
        if (t < nb) p[t] = x - v;
        if (t == nb - 1) p[nb] = x;
        __syncthreads();
    }
}

__global__ void scan_p3(const int* __restrict__ degF, int NF, const int* __restrict__ pF,
                        int* __restrict__ offF, int* __restrict__ curF,
                        const int* __restrict__ degV, int NV, const int* __restrict__ pV,
                        int* __restrict__ offV, int* __restrict__ curV)
{
    const int* deg = blockIdx.y ? degV : degF;
    const int* part = blockIdx.y ? pV : pF;
    int* offs = blockIdx.y ? offV : offF;
    int* cur  = blockIdx.y ? curV : curF;
    const int N = blockIdx.y ? NV : NF;
    if (blockIdx.x * 1024 >= N) return;
    int base = blockIdx.x * 1024 + threadIdx.x * 4;
    int4 v = load4_guard(deg, base, N);
    int s = v.x + v.y + v.z + v.w;
    const int lane = threadIdx.x & 31, w = threadIdx.x >> 5;
    int x = s;
#pragma unroll
    for (int o = 1; o < 32; o <<= 1) {
        int y = __shfl_up_sync(~0u, x, o);
        if (lane >= o) x += y;
    }
    __shared__ int ws[8];
    if (lane == 31) ws[w] = x;
    __syncthreads();
    if (threadIdx.x == 0) {
        int run = 0;
#pragma unroll
        for (int i = 0; i < 8; i++) { int t = ws[i]; ws[i] = run; run += t; }
    }
    __syncthreads();
    int excl = (x - s) + ws[w] + part[blockIdx.x];
    int o0 = excl, o1 = o0 + v.x, o2 = o1 + v.y, o3 = o2 + v.z;
    if (base < N)     { offs[base] = o0;     cur[base] = o0; }
    if (base + 1 < N) { offs[base + 1] = o1; cur[base + 1] = o1; }
    if (base + 2 < N) { offs[base + 2] = o2; cur[base + 2] = o2; }
    if (base + 3 < N) { offs[base + 3] = o3; cur[base + 3] = o3; }
    if (blockIdx.x == 0 && threadIdx.x == 0) offs[N] = part[(N + 1023) >> 10];
}

__global__ void scatter_kernel(const int* __restrict__ src, const int* __restrict__ dst, int E,
                               int* __restrict__ curV, int* __restrict__ curF,
                               int* __restrict__ adjV, int* __restrict__ adjF)
{
    int e = blockIdx.x * blockDim.x + threadIdx.x;
    if (e < E) {
        int s = src[e], d = dst[e];
        adjF[atomicAdd(&curF[d], 1)] = s;
        adjV[atomicAdd(&curV[s], 1)] = d;
    }
}

// ---------------- CSR gather-reduce over fp16 projections (8-edge unroll) ----------------
__device__ __forceinline__ float4 h4f(uint2 raw) {
    __half2 h0 = *reinterpret_cast<__half2*>(&raw.x);
    __half2 h1 = *reinterpret_cast<__half2*>(&raw.y);
    float2 f0 = __half22float2(h0);
    float2 f1 = __half22float2(h1);
    return make_float4(f0.x, f0.y, f1.x, f1.y);
}
__global__ void csr_reduce_kernel(const int* __restrict__ offs, const int* __restrict__ adj,
                                  const __half* __restrict__ Pself, const __half* __restrict__ Pother,
                                  const float* __restrict__ bias, __half* __restrict__ out, int N)
{
    int w = (blockIdx.x * blockDim.x + threadIdx.x) >> 5;
    int lane = threadIdx.x & 31;
    if (w >= N) return;
    const int c = lane * 4;
    float4 s = h4f(*reinterpret_cast<const uint2*>(Pself + (size_t)w * 128 + c));
    float4 b = *reinterpret_cast<const float4*>(bias + c);
    s.x += b.x; s.y += b.y; s.z += b.z; s.w += b.w;
    float4 acc = make_float4(0.f, 0.f, 0.f, 0.f);
    int e = offs[w], e1 = offs[w + 1];
    for (; e + 7 < e1; e += 8) {
        int n[8];
#pragma unroll
        for (int q = 0; q < 8; q++) n[q] = __ldg(adj + e + q);
        uint2 raw[8];
#pragma unroll
        for (int q = 0; q < 8; q++)
            raw[q] = *reinterpret_cast<const uint2*>(Pother + (size_t)n[q] * 128 + c);
#pragma unroll
        for (int q = 0; q < 8; q++) {
            float4 o = h4f(raw[q]);
            acc.x += fmaxf(s.x + o.x, 0.f);
            acc.y += fmaxf(s.y + o.y, 0.f);
            acc.z += fmaxf(s.z + o.z, 0.f);
            acc.w += fmaxf(s.w + o.w, 0.f);
        }
    }
    for (; e < e1; e++) {
        int n0 = __ldg(adj + e);
        float4 o = h4f(*reinterpret_cast<const uint2*>(Pother + (size_t)n0 * 128 + c));
        acc.x += fmaxf(s.x + o.x, 0.f);
        acc.y += fmaxf(s.y + o.y, 0.f);
        acc.z += fmaxf(s.z + o.z, 0.f);
        acc.w += fmaxf(s.w + o.w, 0.f);
    }
    __half2 h0 = __floats2half2_rn(acc.x, acc.y);
    __half2 h1 = __floats2half2_rn(acc.z, acc.w);
    uint2 u;
    u.x = *reinterpret_cast<uint32_t*>(&h0);
    u.y = *reinterpret_cast<uint32_t*>(&h1);
    *reinterpret_cast<uint2*>(out + (size_t)w * 128 + c) = u;
}

// ---------------- global node ----------------
__global__ void gate_kernel(const float* __restrict__ F, const float* __restrict__ Wg,
                            const float* __restrict__ bg, float* __restrict__ gate, int N)
{
    int w = (blockIdx.x * blockDim.x + threadIdx.x) >> 5;
    int lane = threadIdx.x & 31;
    if (w >= N) return;
    float4 f = *reinterpret_cast<const float4*>(F + (size_t)w * 128 + lane * 4);
    float4 g = *reinterpret_cast<const float4*>(Wg + lane * 4);
    float p = f.x * g.x + f.y * g.y + f.z * g.z + f.w * g.w;
#pragma unroll
    for (int d = 16; d; d >>= 1) p += __shfl_down_sync(~0u, p, d);
    if (lane == 0) gate[w] = p + bg[0];
}

__global__ void bounds_kernel(const int* __restrict__ batch, int NF, int G, int* __restrict__ bnd)
{
    int g = threadIdx.x;
    if (g > G) return;
    int lo = 0, hi = NF;
    while (lo < hi) { int mid = (lo + hi) >> 1; if (batch[mid] < g) lo = mid + 1; else hi = mid; }
    bnd[g] = lo;
}

__global__ void group_kernel(const float* __restrict__ gate, const int* __restrict__ bnd,
                             const float* __restrict__ F, float* __restrict__ ebuf,
                             float* __restrict__ wsum)
{
    __shared__ float red[256];
    __shared__ float s_mx, s_den;
    const int g = blockIdx.x;
    const int s = bnd[g], e = bnd[g + 1];
    const int t = threadIdx.x;
    float mx = -1e30f;
    for (int i = s + t; i < e; i += 256) mx = fmaxf(mx, gate[i]);
    red[t] = mx; __syncthreads();
    for (int o = 128; o; o >>= 1) { if (t < o) red[t] = fmaxf(red[t], red[t + o]); __syncthreads(); }
    if (t == 0) s_mx = red[0];
    __syncthreads();
    float den = 0.f;
    for (int i = s + t; i < e; i += 256) { float ex = __expf(gate[i] - s_mx); ebuf[i] = ex; den += ex; }
    red[t] = den; __syncthreads();
    for (int o = 128; o; o >>= 1) { if (t < o) red[t] += red[t + o]; __syncthreads(); }
    if (t == 0) s_den = red[0];
    __syncthreads();
    if (t < 128) {
        float acc = 0.f;
        for (int i = s; i < e; i++) acc += ebuf[i] * F[(size_t)i * 128 + t];
        wsum[g * 128 + t] = (e > s) ? (acc / s_den) : 0.f;
    }
}

__global__ void att_project(const float* __restrict__ wsum, const float* __restrict__ Wt,
                            const float* __restrict__ bt, const int* __restrict__ bnd,
                            float* __restrict__ outT)
{
    __shared__ float ws[128];
    const int g = blockIdx.x;
    const int t = threadIdx.x;
    ws[t] = wsum[g * 128 + t];
    __syncthreads();
    const bool nonempty = bnd[g + 1] > bnd[g];
    float acc = 0.f;
#pragma unroll 8
    for (int k = 0; k < 128; k++) acc += ws[k] * Wt[(size_t)k * 128 + t];
    outT[g * 128 + t] = nonempty ? (acc + bt[t]) : 0.f;
}

// ---------------- launch ----------------
extern "C" void kernel_launch(void* const* d_in, const int* in_sizes, int n_in,
                              void* d_out, int out_size)
{
    const float* V_in  = (const float*)d_in[0];
    const float* F_in  = (const float*)d_in[1];
    const int*   eidx  = (const int*)d_in[2];
    const int*   batch = (const int*)d_in[4];
    const float* Wm_vf = (const float*)d_in[5];
    const float* bm_vf = (const float*)d_in[6];
    const float* Wc_vf = (const float*)d_in[7];
    const float* bc_vf = (const float*)d_in[8];
    const float* Wm_fv = (const float*)d_in[9];
    const float* bm_fv = (const float*)d_in[10];
    const float* Wc_fv = (const float*)d_in[11];
    const float* bc_fv = (const float*)d_in[12];
    const float* Wg    = (const float*)d_in[13];
    const float* bg    = (const float*)d_in[14];
    const float* Wt    = (const float*)d_in[15];
    const float* bt    = (const float*)d_in[16];
    const float* Wl    = (const float*)d_in[17];
    const float* bl    = (const float*)d_in[18];

    const int NV = in_sizes[0] / D128;
    const int NF = in_sizes[1] / D128;
    const int E  = in_sizes[2] / 2;
    const int G  = out_size / D128 - NV - NF;
    const int* src  = eidx;
    const int* dstf = eidx + E;

    float *gatt, *gatt2, *gateArr, *ebuf;
    __half *bufA, *bufB, *bufC, *bufD, *aggrF, *aggrV, *Vc, *Fc, *WTh;
    int *offF, *offV, *curF, *curV, *adjF, *adjV, *bnd, *pF, *pV;
    cudaGetSymbolAddress((void**)&bufA,  d_bufA);
    cudaGetSymbolAddress((void**)&bufB,  d_bufB);
    cudaGetSymbolAddress((void**)&bufC,  d_bufC);
    cudaGetSymbolAddress((void**)&bufD,  d_bufD);
    cudaGetSymbolAddress((void**)&aggrF, d_aggrF);
    cudaGetSymbolAddress((void**)&aggrV, d_aggrV);
    cudaGetSymbolAddress((void**)&Vc,    d_Vc);
    cudaGetSymbolAddress((void**)&Fc,    d_Fc);
    cudaGetSymbolAddress((void**)&WTh,   d_WTh);
    cudaGetSymbolAddress((void**)&gatt,  d_gatt);
    cudaGetSymbolAddress((void**)&gatt2, d_gatt2);
    cudaGetSymbolAddress((void**)&gateArr, d_gate);
    cudaGetSymbolAddress((void**)&ebuf,  d_ebuf);
    cudaGetSymbolAddress((void**)&offF,  d_offF);
    cudaGetSymbolAddress((void**)&offV,  d_offV);
    cudaGetSymbolAddress((void**)&curF,  d_curF);
    cudaGetSymbolAddress((void**)&curV,  d_curV);
    cudaGetSymbolAddress((void**)&adjF,  d_adjF);
    cudaGetSymbolAddress((void**)&adjV,  d_adjV);
    cudaGetSymbolAddress((void**)&bnd,   d_bnd);
    cudaGetSymbolAddress((void**)&pF,    d_partF);
    cudaGetSymbolAddress((void**)&pV,    d_partV);

    const size_t SHM = (size_t)2 * STGH * 2;   // 40960 bytes
    cudaFuncSetAttribute(gemm_mma, cudaFuncAttributeMaxDynamicSharedMemorySize, (int)SHM);

    const size_t L_STRIDE = 131072;

    // ---- launch #1: fused weight transposes (fp16) ----
    TJobs jobs{};
    int nj = 0;
    for (int l = 0; l < 2; l++) {
        const float* WmVF = Wm_vf + (size_t)l * 256 * 128;
        const float* WmFV = Wm_fv + (size_t)l * 256 * 128;
        const float* WcVF = Wc_vf + (size_t)l * 256 * 128;
        const float* WcFV = Wc_fv + (size_t)l * 256 * 128;
        __half* msgF = WTh + l * L_STRIDE;
        __half* msgV = msgF + 32768;
        __half* updF = msgF + 65536;
        __half* updV = msgF + 98304;
        jobs.src[nj] = WmVF;             jobs.dst[nj] = msgF;             jobs.K[nj++] = 128;  // Pf
        jobs.src[nj] = WmFV + 128 * 128; jobs.dst[nj] = msgF + 128 * 128; jobs.K[nj++] = 128;  // Qf
        jobs.src[nj] = WmVF + 128 * 128; jobs.dst[nj] = msgV;             jobs.K[nj++] = 128;  // Pv
        jobs.src[nj] = WmFV;             jobs.dst[nj] = msgV + 128 * 128; jobs.K[nj++] = 128;  // Qv
        jobs.src[nj] = WcVF;             jobs.dst[nj] = updF;             jobs.K[nj++] = 256;
        jobs.src[nj] = WcFV;             jobs.dst[nj] = updV;             jobs.K[nj++] = 256;
    }
    __half* wl_t = WTh + 278528;
    jobs.src[nj] = Wl; jobs.dst[nj] = wl_t; jobs.K[nj++] = 128;   // top half of Wl (g_prev = 0)
    transpose_all<<<dim3(8, 4, nj), dim3(32, 8)>>>(jobs);

    // ---- CSR build part 1 ----
    cudaMemsetAsync(curF, 0, (size_t)NF * sizeof(int));
    cudaMemsetAsync(curV, 0, (size_t)NV * sizeof(int));
    hist_kernel<<<(E + 255) / 256, 256>>>(src, dstf, E, curV, curF);
    const int nbF = (NF + 1023) >> 10, nbV = (NV + 1023) >> 10;
    const int nbMax = nbF > nbV ? nbF : nbV;
    scan_p1<<<dim3(nbMax, 2), 256>>>(curF, NF, pF, curV, NV, pV);

    const int gF = (NF + 127) / 128;
    const int gV = (NV + 127) / 128;
    const int gMax = gF > gV ? gF : gV;

    float* outV_final = (float*)d_out;
    float* outF_final = (float*)d_out + (size_t)NV * D128;
    float* g_out      = (float*)d_out + (size_t)(NV + NF) * D128;

    // ---- launch #6 (ncu capture slot): layer-0 merged projections ----
    {
        GParams pp{};
        pp.K = 128;
        pp.j[0] = { F_in, nullptr, WTh,         nullptr, nullptr, bufA, bufC, NF, 0, 1, 0, 0, 0 };
        pp.j[1] = { V_in, nullptr, WTh + 32768, nullptr, nullptr, bufB, bufD, NV, 0, 1, 0, 0, 0 };
        gemm_mma<<<dim3(gMax, 2, 2), 256, SHM>>>(pp);
    }

    // ---- CSR build part 2 ----
    scan_p2<<<1, 128>>>(pF, nbF, pV, nbV);
    scan_p3<<<dim3(nbMax, 2), 256>>>(curF, NF, pF, offF, curF, curV, NV, pV, offV, curV);
    scatter_kernel<<<(E + 255) / 256, 256>>>(src, dstf, E, curV, curF, adjV, adjF);

    const void* Fp = F_in;  int fph = 0;
    const void* Vp = V_in;  int vph = 0;

    for (int l = 0; l < 2; l++) {
        __half* msgF = WTh + l * L_STRIDE;
        __half* msgV = msgF + 32768;
        __half* updF = msgF + 65536;
        __half* updV = msgF + 98304;

        if (l > 0) {
            GParams pp{};
            pp.K = 128;
            pp.j[0] = { Fp, nullptr, msgF, nullptr, nullptr, bufA, bufC, NF, 0, 1, fph, 0, 0 };
            pp.j[1] = { Vp, nullptr, msgV, nullptr, nullptr, bufB, bufD, NV, 0, 1, vph, 0, 0 };
            gemm_mma<<<dim3(gMax, 2, 2), 256, SHM>>>(pp);
        }

        // aggregations — SEPARATE launches (concurrent gathers thrash L2)
        csr_reduce_kernel<<<(NF + 7) / 8, 256>>>(offF, adjF, bufA, bufB, bm_vf + l * 128, aggrF, NF);
        csr_reduce_kernel<<<(NV + 7) / 8, 256>>>(offV, adjV, bufD, bufC, bm_fv + l * 128, aggrV, NV);

        // merged updates
        GParams up{};
        up.K = 256;
        if (l == 0) {
            up.j[0] = { Fp, aggrF, updF, bc_vf, nullptr, Fc, nullptr, NF, 1, 1, fph, 1, 0 };
            up.j[1] = { Vp, aggrV, updV, bc_fv, Vp,      Vc, nullptr, NV, 1, 1, vph, 1, vph };
            gemm_mma<<<dim3(gMax, 1, 2), 256, SHM>>>(up);
            Fp = Fc; fph = 1;
            Vp = Vc; vph = 1;
        } else {
            up.j[0] = { Fp, aggrF, updF, bc_vf + 128, nullptr, outF_final, nullptr, NF, 1, 0, fph, 1, 0 };
            up.j[1] = { Vp, aggrV, updV, bc_fv + 128, Vp,      outV_final, nullptr, NV, 1, 0, vph, 1, vph };
            gemm_mma<<<dim3(gMax, 1, 2), 256, SHM>>>(up);
        }
    }

    // ---- global node (attention GEMM folded; final F is fp32 in d_out) ----
    gate_kernel<<<(NF + 7) / 8, 256>>>(outF_final, Wg, bg, gateArr, NF);
    bounds_kernel<<<1, 128>>>(batch, NF, G, bnd);
    group_kernel<<<G, 256>>>(gateArr, bnd, outF_final, ebuf, gatt);
    att_project<<<G, 128>>>(gatt, Wt, bt, bnd, gatt2);
    {
        GParams gp{};
        gp.K = 128;
        gp.j[0] = { gatt2, nullptr, wl_t, bl, nullptr, g_out, nullptr, G, 1, 0, 0, 0, 0 };
        gp.j[1] = gp.j[0];
        gemm_mma<<<dim3(1, 1, 1), 256, SHM>>>(gp);   // g = relu(g_att@Wl_top + bl)
    }
}

// round 16
// speedup vs baseline: 1.0107x; 1.0107x over previous
#include <cuda_runtime.h>
#include <cuda_fp16.h>
#include <cstdint>
#include <cstddef>

#define MAXN 100000
#define MAXE 800000
#define D128 128

// ---------------- scratch (no allocs allowed) ----------------
__device__ __half d_bufA[(size_t)MAXN * D128];  // Pf (fp16)
__device__ __half d_bufB[(size_t)MAXN * D128];  // Pv
__device__ __half d_bufC[(size_t)MAXN * D128];  // Qf
__device__ __half d_bufD[(size_t)MAXN * D128];  // Qv
__device__ __half d_aggrF[(size_t)MAXN * D128]; // fp16 aggregates
__device__ __half d_aggrV[(size_t)MAXN * D128];
__device__ __half d_Vc[(size_t)MAXN * D128];    // fp16 layer-0 outputs
__device__ __half d_Fc[(size_t)MAXN * D128];
__device__ __half d_WTh[294912];                // pre-transposed weights (fp16)
__device__ float d_gatt[64 * D128];
__device__ float d_gatt2[64 * D128];
__device__ float d_gate[MAXN];
__device__ float d_ebuf[MAXN];
__device__ int   d_offF[MAXN + 1];
__device__ int   d_offV[MAXN + 1];
__device__ int   d_curF[MAXN];
__device__ int   d_curV[MAXN];
__device__ int   d_adjF[MAXE];
__device__ int   d_adjV[MAXE];
__device__ int   d_bnd[65 + 4];
__device__ int   d_partF[132];
__device__ int   d_partV[132];

// ---------------- PTX helpers ----------------
__device__ __forceinline__ uint32_t smem_u32(const void* p) {
    uint32_t a;
    asm("{ .reg .u64 t; cvta.to.shared.u64 t, %1; cvt.u32.u64 %0, t; }" : "=r"(a) : "l"(p));
    return a;
}
__device__ __forceinline__ void ldsm_x4(uint32_t& r0, uint32_t& r1, uint32_t& r2, uint32_t& r3, uint32_t addr) {
    asm volatile("ldmatrix.sync.aligned.m8n8.x4.shared.b16 {%0,%1,%2,%3}, [%4];"
                 : "=r"(r0), "=r"(r1), "=r"(r2), "=r"(r3) : "r"(addr));
}
__device__ __forceinline__ void mma_f16(float* c, const uint32_t* a, uint32_t b0, uint32_t b1) {
    asm volatile(
        "mma.sync.aligned.m16n8k16.row.col.f32.f16.f16.f32 "
        "{%0,%1,%2,%3}, {%4,%5,%6,%7}, {%8,%9}, {%0,%1,%2,%3};"
        : "+f"(c[0]), "+f"(c[1]), "+f"(c[2]), "+f"(c[3])
        : "r"(a[0]), "r"(a[1]), "r"(a[2]), "r"(a[3]), "r"(b0), "r"(b1));
}

// ---------------- multi-job fp16 GEMM: 256 thr, warp tile 32x64, BK=32, 2 CTA/SM ----------------
struct GJob {
    const void* A0; const void* A1; const __half* WT;
    const float* bias; const void* Res;
    void* Out0; void* Out1;
    int M; int relu; int out16; int a0h; int a1h; int resh;
};
struct GParams { GJob j[2]; int K; };

#define PITH 40
#define STGH (2 * 128 * PITH)
__global__ void __launch_bounds__(256, 2) gemm_mma(GParams P)
{
    extern __shared__ __align__(16) char smc[];
    const GJob J = P.j[blockIdx.z];
    const int K = P.K;
    const int M = J.M;
    const int rowBase = blockIdx.x * 128;
    if (rowBase >= M) return;
    const int tid  = threadIdx.x;
    const int lane = tid & 31;
    const int warp = tid >> 5;
    const int wm = warp & 3;
    const int wn = warp >> 2;
    const __half* WTb = J.WT + (size_t)blockIdx.y * 128 * K;
    void* Outv = (blockIdx.y == 0) ? J.Out0 : J.Out1;

    const int lr = tid >> 3;
    const int lc = (tid & 7) << 2;

    const uint32_t smbase = smem_u32(smc);
    const uint32_t aoffB = (uint32_t)(((wm * 32 + (lane & 15)) * PITH + ((lane >> 4) << 3)) * 2);
    const uint32_t boffB = (uint32_t)(((wn * 64 + ((lane >> 4) << 3) + (lane & 7)) * PITH
                                      + (((lane >> 3) & 1) << 3)) * 2);

    float acc[2][8][4];
#pragma unroll
    for (int mt = 0; mt < 2; mt++)
#pragma unroll
        for (int nt = 0; nt < 8; nt++)
#pragma unroll
            for (int j = 0; j < 4; j++) acc[mt][nt][j] = 0.f;

    const int nch = K >> 5;
    float4 ra[4];
    uint2 rh[4];
    int cur_ah = 0;

#define LDG_A(ck)                                                                      \
    {                                                                                  \
        int kg = (ck) * 32;                                                            \
        const void* Ap = J.A0; cur_ah = J.a0h;                                         \
        if (kg >= 128) { Ap = J.A1; cur_ah = J.a1h; kg -= 128; }                       \
        if (cur_ah) {                                                                  \
            const __half* A16 = (const __half*)Ap;                                     \
            _Pragma("unroll")                                                          \
            for (int h = 0; h < 4; h++) {                                              \
                int r = lr + 32 * h;                                                   \
                int grow = rowBase + r;                                                \
                uint2 z = make_uint2(0u, 0u);                                          \
                if (grow < M) z = *reinterpret_cast<const uint2*>(A16 + (size_t)grow * 128 + kg + lc); \
                rh[h] = z;                                                             \
            }                                                                          \
        } else {                                                                       \
            const float* A32 = (const float*)Ap;                                       \
            _Pragma("unroll")                                                          \
            for (int h = 0; h < 4; h++) {                                              \
                int r = lr + 32 * h;                                                   \
                int grow = rowBase + r;                                                \
                float4 v = make_float4(0.f, 0.f, 0.f, 0.f);                            \
                if (grow < M) v = *reinterpret_cast<const float4*>(A32 + (size_t)grow * 128 + kg + lc); \
                ra[h] = v;                                                             \
            }                                                                          \
        }                                                                              \
    }

#define STS_A(s)                                                                       \
    {                                                                                  \
        char* stA = smc + (size_t)(s) * STGH * 2;                                      \
        if (cur_ah) {                                                                  \
            _Pragma("unroll")                                                          \
            for (int h = 0; h < 4; h++) {                                              \
                int r = lr + 32 * h;                                                   \
                *reinterpret_cast<uint2*>(stA + (size_t)(r * PITH + lc) * 2) = rh[h];  \
            }                                                                          \
        } else {                                                                       \
            _Pragma("unroll")                                                          \
            for (int h = 0; h < 4; h++) {                                              \
                int r = lr + 32 * h;                                                   \
                __half2 h0 = __floats2half2_rn(ra[h].x, ra[h].y);                      \
                __half2 h1 = __floats2half2_rn(ra[h].z, ra[h].w);                      \
                uint2 u;                                                               \
                u.x = *reinterpret_cast<uint32_t*>(&h0);                               \
                u.y = *reinterpret_cast<uint32_t*>(&h1);                               \
                *reinterpret_cast<uint2*>(stA + (size_t)(r * PITH + lc) * 2) = u;      \
            }                                                                          \
        }                                                                              \
    }

#define CPA_B(ck, s)                                                                   \
    {                                                                                  \
        uint32_t stB = smbase + (uint32_t)((s) * STGH + 128 * PITH) * 2;               \
        int n = tid >> 1;                                                              \
        int q = tid & 1;                                                               \
        const __half* s0 = WTb + (size_t)n * K + (ck) * 32 + q * 16;                   \
        uint32_t d0 = stB + (uint32_t)(n * PITH + q * 16) * 2;                         \
        asm volatile("cp.async.ca.shared.global [%0], [%1], 16;" :: "r"(d0), "l"(s0)); \
        asm volatile("cp.async.ca.shared.global [%0], [%1], 16;" :: "r"(d0 + 16), "l"(s0 + 8)); \
        asm volatile("cp.async.commit_group;");                                        \
    }

    LDG_A(0);
    CPA_B(0, 0);
    STS_A(0);
    asm volatile("cp.async.wait_group 0;" ::: "memory");
    __syncthreads();

    for (int ck = 0; ck < nch; ck++) {
        const int s = ck & 1;
        if (ck + 1 < nch) {
            LDG_A(ck + 1);
            CPA_B(ck + 1, s ^ 1);
        }
        const uint32_t smA = smbase + (uint32_t)(s * STGH) * 2;
        const uint32_t smB = smA + (uint32_t)(128 * PITH) * 2;
#pragma unroll
        for (int kstep = 0; kstep < 2; kstep++) {
            uint32_t a[2][4];
            ldsm_x4(a[0][0], a[0][1], a[0][2], a[0][3], smA + aoffB + kstep * 32);
            ldsm_x4(a[1][0], a[1][1], a[1][2], a[1][3], smA + aoffB + 16 * PITH * 2 + kstep * 32);
            uint32_t b[4][4];
#pragma unroll
            for (int p = 0; p < 4; p++)
                ldsm_x4(b[p][0], b[p][1], b[p][2], b[p][3],
                        smB + boffB + (uint32_t)(p * 16 * PITH * 2) + kstep * 32);
#pragma unroll
            for (int mt = 0; mt < 2; mt++)
#pragma unroll
                for (int nt = 0; nt < 8; nt++)
                    mma_f16(acc[mt][nt], a[mt], b[nt >> 1][(nt & 1) * 2], b[nt >> 1][(nt & 1) * 2 + 1]);
        }
        if (ck + 1 < nch) {
            STS_A(s ^ 1);
            asm volatile("cp.async.wait_group 0;" ::: "memory");
            __syncthreads();
        }
    }

    // epilogue
    const int col2 = (lane & 3) * 2;
#pragma unroll
    for (int mt = 0; mt < 2; mt++) {
        const int r0 = rowBase + wm * 32 + mt * 16 + (lane >> 2);
#pragma unroll
        for (int nt = 0; nt < 8; nt++) {
            int col = wn * 64 + nt * 8 + col2;
            float v0 = acc[mt][nt][0], v1 = acc[mt][nt][1];
            float v2 = acc[mt][nt][2], v3 = acc[mt][nt][3];
            if (J.bias) {
                float b0 = J.bias[col], b1 = J.bias[col + 1];
                v0 += b0; v1 += b1; v2 += b0; v3 += b1;
            }
            if (J.relu) {
                v0 = fmaxf(v0, 0.f); v1 = fmaxf(v1, 0.f);
                v2 = fmaxf(v2, 0.f); v3 = fmaxf(v3, 0.f);
            }
            if (J.Res) {
                if (J.resh) {
                    const __half* R = (const __half*)J.Res;
                    if (r0 < M) {
                        __half2 hh = *reinterpret_cast<const __half2*>(R + (size_t)r0 * 128 + col);
                        float2 rr = __half22float2(hh);
                        v0 += rr.x; v1 += rr.y;
                    }
                    if (r0 + 8 < M) {
                        __half2 hh = *reinterpret_cast<const __half2*>(R + (size_t)(r0 + 8) * 128 + col);
                        float2 rr = __half22float2(hh);
                        v2 += rr.x; v3 += rr.y;
                    }
                } else {
                    const float* R = (const float*)J.Res;
                    if (r0 < M) {
                        float2 rr = *reinterpret_cast<const float2*>(R + (size_t)r0 * 128 + col);
                        v0 += rr.x; v1 += rr.y;
                    }
                    if (r0 + 8 < M) {
                        float2 rr = *reinterpret_cast<const float2*>(R + (size_t)(r0 + 8) * 128 + col);
                        v2 += rr.x; v3 += rr.y;
                    }
                }
            }
            if (J.out16) {
                __half* Out = (__half*)Outv;
                if (r0 < M)
                    *reinterpret_cast<__half2*>(Out + (size_t)r0 * 128 + col) = __floats2half2_rn(v0, v1);
                if (r0 + 8 < M)
                    *reinterpret_cast<__half2*>(Out + (size_t)(r0 + 8) * 128 + col) = __floats2half2_rn(v2, v3);
            } else {
                float* Out = (float*)Outv;
                if (r0 < M)
                    *reinterpret_cast<float2*>(Out + (size_t)r0 * 128 + col) = make_float2(v0, v1);
                if (r0 + 8 < M)
                    *reinterpret_cast<float2*>(Out + (size_t)(r0 + 8) * 128 + col) = make_float2(v2, v3);
            }
        }
    }
}

// ---------------- fused weight transposes ----------------
struct TJobs {
    const float* src[16];
    __half* dst[16];
    int K[16];
};
__global__ void transpose_all(TJobs jobs)
{
    __shared__ float t[32][33];
    const int j = blockIdx.z;
    const int K = jobs.K[j];
    const int kb = blockIdx.x * 32;
    if (kb >= K) return;
    const float* src = jobs.src[j];
    __half* dst = jobs.dst[j];
    const int nb = blockIdx.y * 32;
    const int x = threadIdx.x, y = threadIdx.y;
    for (int yy = y; yy < 32; yy += 8) t[yy][x] = src[(size_t)(kb + yy) * 128 + nb + x];
    __syncthreads();
    for (int yy = y; yy < 32; yy += 8)
        dst[(size_t)(nb + yy) * K + kb + x] = __float2half_rn(t[x][yy]);
}

// ---------------- CSR build ----------------
__global__ void hist_kernel(const int* __restrict__ src, const int* __restrict__ dst, int E,
                            int* __restrict__ degV, int* __restrict__ degF)
{
    int e = blockIdx.x * blockDim.x + threadIdx.x;
    if (e < E) {
        atomicAdd(&degV[src[e]], 1);
        atomicAdd(&degF[dst[e]], 1);
    }
}

__device__ __forceinline__ int4 load4_guard(const int* p, int base, int N)
{
    int4 v = make_int4(0, 0, 0, 0);
    if (base + 3 < N) v = *reinterpret_cast<const int4*>(p + base);
    else if (base < N) {
        v.x = p[base];
        if (base + 1 < N) v.y = p[base + 1];
        if (base + 2 < N) v.z = p[base + 2];
    }
    return v;
}

__global__ void scan_p1(const int* __restrict__ degF, int NF, int* __restrict__ pF,
                        const int* __restrict__ degV, int NV, int* __restrict__ pV)
{
    const int* deg = blockIdx.y ? degV : degF;
    int* part = blockIdx.y ? pV : pF;
    const int N = blockIdx.y ? NV : NF;
    if (blockIdx.x * 1024 >= N) return;
    int base = blockIdx.x * 1024 + threadIdx.x * 4;
    int4 v = load4_guard(deg, base, N);
    int s = v.x + v.y + v.z + v.w;
#pragma unroll
    for (int d = 16; d; d >>= 1) s += __shfl_down_sync(~0u, s, d);
    __shared__ int ws[8];
    if ((threadIdx.x & 31) == 0) ws[threadIdx.x >> 5] = s;
    __syncthreads();
    if (threadIdx.x == 0) {
        int tt = 0;
#pragma unroll
        for (int i = 0; i < 8; i++) tt += ws[i];
        part[blockIdx.x] = tt;
    }
}

__global__ void scan_p2(int* __restrict__ pF, int nbF, int* __restrict__ pV, int nbV)
{
    __shared__ int sh[128];
    const int t = threadIdx.x;
    for (int sel = 0; sel < 2; sel++) {
        int* p = sel ? pV : pF;
        const int nb = sel ? nbV : nbF;
        int v = (t < nb) ? p[t] : 0;
        sh[t] = v;
        __syncthreads();
        int x = v;
        for (int o = 1; o < 128; o <<= 1) {
            int y = (t >= o) ? sh[t - o] : 0;
            __syncthreads();
            x += y;
            sh[t] = x;
            __syncthreads();
        }
        if (t < nb) p[t] = x - v;
        if (t == nb - 1) p[nb] = x;
        __syncthreads();
    }
}

__global__ void scan_p3(const int* __restrict__ degF, int NF, const int* __restrict__ pF,
                        int* __restrict__ offF, int* __restrict__ curF,
                        const int* __restrict__ degV, int NV, const int* __restrict__ pV,
                        int* __restrict__ offV, int* __restrict__ curV)
{
    const int* deg = blockIdx.y ? degV : degF;
    const int* part = blockIdx.y ? pV : pF;
    int* offs = blockIdx.y ? offV : offF;
    int* cur  = blockIdx.y ? curV : curF;
    const int N = blockIdx.y ? NV : NF;
    if (blockIdx.x * 1024 >= N) return;
    int base = blockIdx.x * 1024 + threadIdx.x * 4;
    int4 v = load4_guard(deg, base, N);
    int s = v.x + v.y + v.z + v.w;
    const int lane = threadIdx.x & 31, w = threadIdx.x >> 5;
    int x = s;
#pragma unroll
    for (int o = 1; o < 32; o <<= 1) {
        int y = __shfl_up_sync(~0u, x, o);
        if (lane >= o) x += y;
    }
    __shared__ int ws[8];
    if (lane == 31) ws[w] = x;
    __syncthreads();
    if (threadIdx.x == 0) {
        int run = 0;
#pragma unroll
        for (int i = 0; i < 8; i++) { int t = ws[i]; ws[i] = run; run += t; }
    }
    __syncthreads();
    int excl = (x - s) + ws[w] + part[blockIdx.x];
    int o0 = excl, o1 = o0 + v.x, o2 = o1 + v.y, o3 = o2 + v.z;
    if (base < N)     { offs[base] = o0;     cur[base] = o0; }
    if (base + 1 < N) { offs[base + 1] = o1; cur[base + 1] = o1; }
    if (base + 2 < N) { offs[base + 2] = o2; cur[base + 2] = o2; }
    if (base + 3 < N) { offs[base + 3] = o3; cur[base + 3] = o3; }
    if (blockIdx.x == 0 && threadIdx.x == 0) offs[N] = part[(N + 1023) >> 10];
}

__global__ void scatter_kernel(const int* __restrict__ src, const int* __restrict__ dst, int E,
                               int* __restrict__ curV, int* __restrict__ curF,
                               int* __restrict__ adjV, int* __restrict__ adjF)
{
    int e = blockIdx.x * blockDim.x + threadIdx.x;
    if (e < E) {
        int s = src[e], d = dst[e];
        adjF[atomicAdd(&curF[d], 1)] = s;
        adjV[atomicAdd(&curV[s], 1)] = d;
    }
}

// ---------------- CSR gather-reduce over fp16 projections (4-edge unroll) ----------------
__device__ __forceinline__ float4 h4f(uint2 raw) {
    __half2 h0 = *reinterpret_cast<__half2*>(&raw.x);
    __half2 h1 = *reinterpret_cast<__half2*>(&raw.y);
    float2 f0 = __half22float2(h0);
    float2 f1 = __half22float2(h1);
    return make_float4(f0.x, f0.y, f1.x, f1.y);
}
__global__ void csr_reduce_kernel(const int* __restrict__ offs, const int* __restrict__ adj,
                                  const __half* __restrict__ Pself, const __half* __restrict__ Pother,
                                  const float* __restrict__ bias, __half* __restrict__ out, int N)
{
    int w = (blockIdx.x * blockDim.x + threadIdx.x) >> 5;
    int lane = threadIdx.x & 31;
    if (w >= N) return;
    const int c = lane * 4;
    float4 s = h4f(*reinterpret_cast<const uint2*>(Pself + (size_t)w * 128 + c));
    float4 b = *reinterpret_cast<const float4*>(bias + c);
    s.x += b.x; s.y += b.y; s.z += b.z; s.w += b.w;
    float4 acc = make_float4(0.f, 0.f, 0.f, 0.f);
    int e = offs[w], e1 = offs[w + 1];
    for (; e + 3 < e1; e += 4) {
        int n0 = __ldg(adj + e), n1 = __ldg(adj + e + 1);
        int n2 = __ldg(adj + e + 2), n3 = __ldg(adj + e + 3);
        float4 o0 = h4f(*reinterpret_cast<const uint2*>(Pother + (size_t)n0 * 128 + c));
        float4 o1 = h4f(*reinterpret_cast<const uint2*>(Pother + (size_t)n1 * 128 + c));
        float4 o2 = h4f(*reinterpret_cast<const uint2*>(Pother + (size_t)n2 * 128 + c));
        float4 o3 = h4f(*reinterpret_cast<const uint2*>(Pother + (size_t)n3 * 128 + c));
        acc.x += fmaxf(s.x + o0.x, 0.f) + fmaxf(s.x + o1.x, 0.f) + fmaxf(s.x + o2.x, 0.f) + fmaxf(s.x + o3.x, 0.f);
        acc.y += fmaxf(s.y + o0.y, 0.f) + fmaxf(s.y + o1.y, 0.f) + fmaxf(s.y + o2.y, 0.f) + fmaxf(s.y + o3.y, 0.f);
        acc.z += fmaxf(s.z + o0.z, 0.f) + fmaxf(s.z + o1.z, 0.f) + fmaxf(s.z + o2.z, 0.f) + fmaxf(s.z + o3.z, 0.f);
        acc.w += fmaxf(s.w + o0.w, 0.f) + fmaxf(s.w + o1.w, 0.f) + fmaxf(s.w + o2.w, 0.f) + fmaxf(s.w + o3.w, 0.f);
    }
    for (; e < e1; e++) {
        int n0 = __ldg(adj + e);
        float4 o = h4f(*reinterpret_cast<const uint2*>(Pother + (size_t)n0 * 128 + c));
        acc.x += fmaxf(s.x + o.x, 0.f);
        acc.y += fmaxf(s.y + o.y, 0.f);
        acc.z += fmaxf(s.z + o.z, 0.f);
        acc.w += fmaxf(s.w + o.w, 0.f);
    }
    __half2 h0 = __floats2half2_rn(acc.x, acc.y);
    __half2 h1 = __floats2half2_rn(acc.z, acc.w);
    uint2 u;
    u.x = *reinterpret_cast<uint32_t*>(&h0);
    u.y = *reinterpret_cast<uint32_t*>(&h1);
    *reinterpret_cast<uint2*>(out + (size_t)w * 128 + c) = u;
}

// ---------------- global node ----------------
__global__ void gate_kernel(const float* __restrict__ F, const float* __restrict__ Wg,
                            const float* __restrict__ bg, float* __restrict__ gate, int N)
{
    int w = (blockIdx.x * blockDim.x + threadIdx.x) >> 5;
    int lane = threadIdx.x & 31;
    if (w >= N) return;
    float4 f = *reinterpret_cast<const float4*>(F + (size_t)w * 128 + lane * 4);
    float4 g = *reinterpret_cast<const float4*>(Wg + lane * 4);
    float p = f.x * g.x + f.y * g.y + f.z * g.z + f.w * g.w;
#pragma unroll
    for (int d = 16; d; d >>= 1) p += __shfl_down_sync(~0u, p, d);
    if (lane == 0) gate[w] = p + bg[0];
}

__global__ void bounds_kernel(const int* __restrict__ batch, int NF, int G, int* __restrict__ bnd)
{
    int g = threadIdx.x;
    if (g > G) return;
    int lo = 0, hi = NF;
    while (lo < hi) { int mid = (lo + hi) >> 1; if (batch[mid] < g) lo = mid + 1; else hi = mid; }
    bnd[g] = lo;
}

__global__ void group_kernel(const float* __restrict__ gate, const int* __restrict__ bnd,
                             const float* __restrict__ F, float* __restrict__ ebuf,
                             float* __restrict__ wsum)
{
    __shared__ float red[256];
    __shared__ float s_mx, s_den;
    const int g = blockIdx.x;
    const int s = bnd[g], e = bnd[g + 1];
    const int t = threadIdx.x;
    float mx = -1e30f;
    for (int i = s + t; i < e; i += 256) mx = fmaxf(mx, gate[i]);
    red[t] = mx; __syncthreads();
    for (int o = 128; o; o >>= 1) { if (t < o) red[t] = fmaxf(red[t], red[t + o]); __syncthreads(); }
    if (t == 0) s_mx = red[0];
    __syncthreads();
    float den = 0.f;
    for (int i = s + t; i < e; i += 256) { float ex = __expf(gate[i] - s_mx); ebuf[i] = ex; den += ex; }
    red[t] = den; __syncthreads();
    for (int o = 128; o; o >>= 1) { if (t < o) red[t] += red[t + o]; __syncthreads(); }
    if (t == 0) s_den = red[0];
    __syncthreads();
    if (t < 128) {
        float acc = 0.f;
        for (int i = s; i < e; i++) acc += ebuf[i] * F[(size_t)i * 128 + t];
        wsum[g * 128 + t] = (e > s) ? (acc / s_den) : 0.f;
    }
}

__global__ void att_project(const float* __restrict__ wsum, const float* __restrict__ Wt,
                            const float* __restrict__ bt, const int* __restrict__ bnd,
                            float* __restrict__ outT)
{
    __shared__ float ws[128];
    const int g = blockIdx.x;
    const int t = threadIdx.x;
    ws[t] = wsum[g * 128 + t];
    __syncthreads();
    const bool nonempty = bnd[g + 1] > bnd[g];
    float acc = 0.f;
#pragma unroll 8
    for (int k = 0; k < 128; k++) acc += ws[k] * Wt[(size_t)k * 128 + t];
    outT[g * 128 + t] = nonempty ? (acc + bt[t]) : 0.f;
}

// ---------------- launch ----------------
extern "C" void kernel_launch(void* const* d_in, const int* in_sizes, int n_in,
                              void* d_out, int out_size)
{
    const float* V_in  = (const float*)d_in[0];
    const float* F_in  = (const float*)d_in[1];
    const int*   eidx  = (const int*)d_in[2];
    const int*   batch = (const int*)d_in[4];
    const float* Wm_vf = (const float*)d_in[5];
    const float* bm_vf = (const float*)d_in[6];
    const float* Wc_vf = (const float*)d_in[7];
    const float* bc_vf = (const float*)d_in[8];
    const float* Wm_fv = (const float*)d_in[9];
    const float* bm_fv = (const float*)d_in[10];
    const float* Wc_fv = (const float*)d_in[11];
    const float* bc_fv = (const float*)d_in[12];
    const float* Wg    = (const float*)d_in[13];
    const float* bg    = (const float*)d_in[14];
    const float* Wt    = (const float*)d_in[15];
    const float* bt    = (const float*)d_in[16];
    const float* Wl    = (const float*)d_in[17];
    const float* bl    = (const float*)d_in[18];

    const int NV = in_sizes[0] / D128;
    const int NF = in_sizes[1] / D128;
    const int E  = in_sizes[2] / 2;
    const int G  = out_size / D128 - NV - NF;
    const int* src  = eidx;
    const int* dstf = eidx + E;

    float *gatt, *gatt2, *gateArr, *ebuf;
    __half *bufA, *bufB, *bufC, *bufD, *aggrF, *aggrV, *Vc, *Fc, *WTh;
    int *offF, *offV, *curF, *curV, *adjF, *adjV, *bnd, *pF, *pV;
    cudaGetSymbolAddress((void**)&bufA,  d_bufA);
    cudaGetSymbolAddress((void**)&bufB,  d_bufB);
    cudaGetSymbolAddress((void**)&bufC,  d_bufC);
    cudaGetSymbolAddress((void**)&bufD,  d_bufD);
    cudaGetSymbolAddress((void**)&aggrF, d_aggrF);
    cudaGetSymbolAddress((void**)&aggrV, d_aggrV);
    cudaGetSymbolAddress((void**)&Vc,    d_Vc);
    cudaGetSymbolAddress((void**)&Fc,    d_Fc);
    cudaGetSymbolAddress((void**)&WTh,   d_WTh);
    cudaGetSymbolAddress((void**)&gatt,  d_gatt);
    cudaGetSymbolAddress((void**)&gatt2, d_gatt2);
    cudaGetSymbolAddress((void**)&gateArr, d_gate);
    cudaGetSymbolAddress((void**)&ebuf,  d_ebuf);
    cudaGetSymbolAddress((void**)&offF,  d_offF);
    cudaGetSymbolAddress((void**)&offV,  d_offV);
    cudaGetSymbolAddress((void**)&curF,  d_curF);
    cudaGetSymbolAddress((void**)&curV,  d_curV);
    cudaGetSymbolAddress((void**)&adjF,  d_adjF);
    cudaGetSymbolAddress((void**)&adjV,  d_adjV);
    cudaGetSymbolAddress((void**)&bnd,   d_bnd);
    cudaGetSymbolAddress((void**)&pF,    d_partF);
    cudaGetSymbolAddress((void**)&pV,    d_partV);

    const size_t SHM = (size_t)2 * STGH * 2;   // 40960 bytes
    cudaFuncSetAttribute(gemm_mma, cudaFuncAttributeMaxDynamicSharedMemorySize, (int)SHM);

    const size_t L_STRIDE = 131072;

    // ---- fork: CSR build runs on a side stream, overlapped with transposes + layer-0 projections ----
    cudaStream_t s2;
    cudaStreamCreateWithFlags(&s2, cudaStreamNonBlocking);
    cudaEvent_t evFork, evJoin;
    cudaEventCreateWithFlags(&evFork, cudaEventDisableTiming);
    cudaEventCreateWithFlags(&evJoin, cudaEventDisableTiming);

    cudaEventRecord(evFork, 0);
    cudaStreamWaitEvent(s2, evFork, 0);

    // ---- side stream: full CSR build ----
    cudaMemsetAsync(curF, 0, (size_t)NF * sizeof(int), s2);
    cudaMemsetAsync(curV, 0, (size_t)NV * sizeof(int), s2);
    hist_kernel<<<(E + 255) / 256, 256, 0, s2>>>(src, dstf, E, curV, curF);
    const int nbF = (NF + 1023) >> 10, nbV = (NV + 1023) >> 10;
    const int nbMax = nbF > nbV ? nbF : nbV;
    scan_p1<<<dim3(nbMax, 2), 256, 0, s2>>>(curF, NF, pF, curV, NV, pV);
    scan_p2<<<1, 128, 0, s2>>>(pF, nbF, pV, nbV);
    scan_p3<<<dim3(nbMax, 2), 256, 0, s2>>>(curF, NF, pF, offF, curF, curV, NV, pV, offV, curV);
    scatter_kernel<<<(E + 255) / 256, 256, 0, s2>>>(src, dstf, E, curV, curF, adjV, adjF);
    cudaEventRecord(evJoin, s2);

    // ---- main stream: weight transposes ----
    TJobs jobs{};
    int nj = 0;
    for (int l = 0; l < 2; l++) {
        const float* WmVF = Wm_vf + (size_t)l * 256 * 128;
        const float* WmFV = Wm_fv + (size_t)l * 256 * 128;
        const float* WcVF = Wc_vf + (size_t)l * 256 * 128;
        const float* WcFV = Wc_fv + (size_t)l * 256 * 128;
        __half* msgF = WTh + l * L_STRIDE;
        __half* msgV = msgF + 32768;
        __half* updF = msgF + 65536;
        __half* updV = msgF + 98304;
        jobs.src[nj] = WmVF;             jobs.dst[nj] = msgF;             jobs.K[nj++] = 128;  // Pf
        jobs.src[nj] = WmFV + 128 * 128; jobs.dst[nj] = msgF + 128 * 128; jobs.K[nj++] = 128;  // Qf
        jobs.src[nj] = WmVF + 128 * 128; jobs.dst[nj] = msgV;             jobs.K[nj++] = 128;  // Pv
        jobs.src[nj] = WmFV;             jobs.dst[nj] = msgV + 128 * 128; jobs.K[nj++] = 128;  // Qv
        jobs.src[nj] = WcVF;             jobs.dst[nj] = updF;             jobs.K[nj++] = 256;
        jobs.src[nj] = WcFV;             jobs.dst[nj] = updV;             jobs.K[nj++] = 256;
    }
    __half* wl_t = WTh + 278528;
    jobs.src[nj] = Wl; jobs.dst[nj] = wl_t; jobs.K[nj++] = 128;   // top half of Wl (g_prev = 0)
    transpose_all<<<dim3(8, 4, nj), dim3(32, 8)>>>(jobs);

    const int gF = (NF + 127) / 128;
    const int gV = (NV + 127) / 128;
    const int gMax = gF > gV ? gF : gV;

    float* outV_final = (float*)d_out;
    float* outF_final = (float*)d_out + (size_t)NV * D128;
    float* g_out      = (float*)d_out + (size_t)(NV + NF) * D128;

    // ---- main stream: layer-0 merged projections (overlapped with CSR build) ----
    {
        GParams pp{};
        pp.K = 128;
        pp.j[0] = { F_in, nullptr, WTh,         nullptr, nullptr, bufA, bufC, NF, 0, 1, 0, 0, 0 };
        pp.j[1] = { V_in, nullptr, WTh + 32768, nullptr, nullptr, bufB, bufD, NV, 0, 1, 0, 0, 0 };
        gemm_mma<<<dim3(gMax, 2, 2), 256, SHM>>>(pp);
    }

    // ---- join: CSR adjacency must be ready before the gathers ----
    cudaStreamWaitEvent(0, evJoin, 0);

    const void* Fp = F_in;  int fph = 0;
    const void* Vp = V_in;  int vph = 0;

    for (int l = 0; l < 2; l++) {
        __half* msgF = WTh + l * L_STRIDE;
        __half* msgV = msgF + 32768;
        __half* updF = msgF + 65536;
        __half* updV = msgF + 98304;

        if (l > 0) {
            GParams pp{};
            pp.K = 128;
            pp.j[0] = { Fp, nullptr, msgF, nullptr, nullptr, bufA, bufC, NF, 0, 1, fph, 0, 0 };
            pp.j[1] = { Vp, nullptr, msgV, nullptr, nullptr, bufB, bufD, NV, 0, 1, vph, 0, 0 };
            gemm_mma<<<dim3(gMax, 2, 2), 256, SHM>>>(pp);
        }

        // aggregations — SEPARATE launches (concurrent gathers thrash L2)
        csr_reduce_kernel<<<(NF + 7) / 8, 256>>>(offF, adjF, bufA, bufB, bm_vf + l * 128, aggrF, NF);
        csr_reduce_kernel<<<(NV + 7) / 8, 256>>>(offV, adjV, bufD, bufC, bm_fv + l * 128, aggrV, NV);

        // merged updates
        GParams up{};
        up.K = 256;
        if (l == 0) {
            up.j[0] = { Fp, aggrF, updF, bc_vf, nullptr, Fc, nullptr, NF, 1, 1, fph, 1, 0 };
            up.j[1] = { Vp, aggrV, updV, bc_fv, Vp,      Vc, nullptr, NV, 1, 1, vph, 1, vph };
            gemm_mma<<<dim3(gMax, 1, 2), 256, SHM>>>(up);
            Fp = Fc; fph = 1;
            Vp = Vc; vph = 1;
        } else {
            up.j[0] = { Fp, aggrF, updF, bc_vf + 128, nullptr, outF_final, nullptr, NF, 1, 0, fph, 1, 0 };
            up.j[1] = { Vp, aggrV, updV, bc_fv + 128, Vp,      outV_final, nullptr, NV, 1, 0, vph, 1, vph };
            gemm_mma<<<dim3(gMax, 1, 2), 256, SHM>>>(up);
        }
    }

    // ---- global node (attention GEMM folded; final F is fp32 in d_out) ----
    gate_kernel<<<(NF + 7) / 8, 256>>>(outF_final, Wg, bg, gateArr, NF);
    bounds_kernel<<<1, 128>>>(batch, NF, G, bnd);
    group_kernel<<<G, 256>>>(gateArr, bnd, outF_final, ebuf, gatt);
    att_project<<<G, 128>>>(gatt, Wt, bt, bnd, gatt2);
    {
        GParams gp{};
        gp.K = 128;
        gp.j[0] = { gatt2, nullptr, wl_t, bl, nullptr, g_out, nullptr, G, 1, 0, 0, 0, 0 };
        gp.j[1] = gp.j[0];
        gemm_mma<<<dim3(1, 1, 1), 256, SHM>>>(gp);   // g = relu(g_att@Wl_top + bl)
    }

    cudaEventDestroy(evFork);
    cudaEventDestroy(evJoin);
    cudaStreamDestroy(s2);
}